// round 11
// baseline (speedup 1.0000x reference)
#include <cuda_runtime.h>
#include <cuda_bf16.h>
#include <math.h>
#include <stdint.h>

#define DD   248
#define HH   512
#define NMAX 10000
#define EMAX 100000
#define NNZMAX 4096

// ---------------- scratch (device globals; no allocs allowed) ----------------
__device__ float g_proj[NMAX * DD];
__device__ float g_h2[NMAX * DD];
__device__ __align__(16) __nv_bfloat16 g_fhi[NMAX * DD];
__device__ __align__(16) __nv_bfloat16 g_flo[NMAX * DD];
__device__ __align__(16) __nv_bfloat16 g_agghi[NMAX * DD];
__device__ __align__(16) __nv_bfloat16 g_agglo[NMAX * DD];
__device__ __align__(16) __nv_bfloat16 g_hidhi[NMAX * HH];
__device__ __align__(16) __nv_bfloat16 g_hidlo[NMAX * HH];
__device__ __align__(16) __nv_bfloat16 g_wmhi[DD * DD];
__device__ __align__(16) __nv_bfloat16 g_wmlo[DD * DD];
__device__ __align__(16) __nv_bfloat16 g_w1hi[HH * DD];
__device__ __align__(16) __nv_bfloat16 g_w1lo[HH * DD];
__device__ __align__(16) __nv_bfloat16 g_w2hi[DD * HH];
__device__ __align__(16) __nv_bfloat16 g_w2lo[DD * HH];
// structure-constant CSR
__device__ int   g_rowptr[DD + 1];
__device__ int   g_Is[NNZMAX];
__device__ int   g_Js[NNZMAX];
__device__ float g_Cs[NNZMAX];
// edge CSR (by target node)
__device__ int   g_deg[NMAX];
__device__ int   g_eoff[NMAX + 1];
__device__ int   g_cursor[NMAX];
__device__ int   g_esrc[EMAX];

// ---------------- splits ----------------
__device__ __forceinline__ void split1(const float* __restrict__ x,
                                       __nv_bfloat16* __restrict__ hi,
                                       __nv_bfloat16* __restrict__ lo, int i) {
    float v = x[i];
    __nv_bfloat16 h = __float2bfloat16(v);
    hi[i] = h;
    lo[i] = __float2bfloat16(v - __bfloat162float(h));
}

// launch #1: features split + zero edge-degree counters
__global__ void prep_feat_kernel(const float* __restrict__ F,
                                 __nv_bfloat16* __restrict__ fhi,
                                 __nv_bfloat16* __restrict__ flo,
                                 int nfeat, int nnodes) {
    int i = blockIdx.x * blockDim.x + threadIdx.x;
    int stride = gridDim.x * blockDim.x;
    for (; i < nfeat; i += stride) {
        split1(F, fhi, flo, i);
        if (i < nnodes) g_deg[i] = 0;
    }
}

// launch #2: all weight splits
__global__ void prep_w_kernel(const float* __restrict__ Wmsg,
                              const float* __restrict__ W1,
                              const float* __restrict__ W2,
                              __nv_bfloat16* __restrict__ wmhi, __nv_bfloat16* __restrict__ wmlo,
                              __nv_bfloat16* __restrict__ w1hi, __nv_bfloat16* __restrict__ w1lo,
                              __nv_bfloat16* __restrict__ w2hi, __nv_bfloat16* __restrict__ w2lo) {
    const int s1 = DD * DD;
    const int s2 = HH * DD;
    const int s3 = DD * HH;
    int total = s1 + s2 + s3;
    int i = blockIdx.x * blockDim.x + threadIdx.x;
    int stride = gridDim.x * blockDim.x;
    for (; i < total; i += stride) {
        if (i < s1)            split1(Wmsg, wmhi, wmlo, i);
        else if (i < s1 + s2)  split1(W1, w1hi, w1lo, i - s1);
        else                   split1(W2, w2hi, w2lo, i - s1 - s2);
    }
}

// launch #3: deterministic parallel structure-constant CSR (stable rank-by-scan)
__global__ void build_csr_fast(const int* __restrict__ Iv, const int* __restrict__ Jv,
                               const int* __restrict__ Kv, const float* __restrict__ Cv,
                               int nnz) {
    __shared__ int sK[NNZMAX];
    __shared__ int cnt[DD];
    int tid = threadIdx.x;
    for (int t = tid; t < nnz; t += blockDim.x) sK[t] = Kv[t];
    for (int k = tid; k < DD; k += blockDim.x) cnt[k] = 0;
    __syncthreads();
    for (int t = tid; t < nnz; t += blockDim.x) atomicAdd(&cnt[sK[t]], 1);
    __syncthreads();
    __shared__ int off[DD + 1];
    if (tid == 0) {
        int s = 0;
        for (int k = 0; k < DD; k++) { off[k] = s; s += cnt[k]; }
        off[DD] = s;
    }
    __syncthreads();
    if (blockIdx.x == 0)
        for (int k = tid; k <= DD; k += blockDim.x) g_rowptr[k] = off[k];
    int t = blockIdx.x * blockDim.x + tid;
    if (t < nnz) {
        int k = sK[t];
        int rank = 0;
        for (int t2 = 0; t2 < t; ++t2) rank += (sK[t2] == k);
        int pos = off[k] + rank;
        g_Is[pos] = Iv[t];
        g_Js[pos] = Jv[t];
        g_Cs[pos] = Cv[t];
    }
}

// ---------------- edge CSR build ----------------
__global__ void edge_count_kernel(const int* __restrict__ ei, int E) {
    int e = blockIdx.x * blockDim.x + threadIdx.x;
    if (e < E) atomicAdd(&g_deg[ei[E + e]], 1);
}

// single block, 256 threads: exclusive scan over g_deg -> g_eoff, zero cursors
__global__ void edge_scan_kernel(int nnodes) {
    __shared__ int pref[257];
    int tid = threadIdx.x;
    int per = (nnodes + 255) / 256;
    int b = tid * per;
    int e = min(b + per, nnodes);
    int s = 0;
    for (int i = b; i < e; i++) s += g_deg[i];
    __shared__ int part[256];
    part[tid] = s;
    __syncthreads();
    if (tid == 0) {
        int a = 0;
        for (int i = 0; i < 256; i++) { pref[i] = a; a += part[i]; }
        pref[256] = a;
    }
    __syncthreads();
    int run = pref[tid];
    for (int i = b; i < e; i++) {
        g_eoff[i] = run;
        run += g_deg[i];
        g_cursor[i] = 0;
    }
    if (tid == 0) g_eoff[nnodes] = pref[256];
}

__global__ void edge_fill_kernel(const int* __restrict__ ei, int E) {
    int e = blockIdx.x * blockDim.x + threadIdx.x;
    if (e < E) {
        int t = ei[E + e];
        int pos = g_eoff[t] + atomicAdd(&g_cursor[t], 1);
        g_esrc[pos] = ei[e];
    }
}

// ---------------- fused gather (segment-sum of proj rows) + Lie bracket ------
// One block per node: gather incoming proj rows via coalesced float4 loads,
// then apply CSR bracket and emit bf16 split of agg.
__global__ void gather_bracket_kernel(const float* __restrict__ proj,
                                      const float* __restrict__ F,
                                      __nv_bfloat16* __restrict__ Ahi,
                                      __nv_bfloat16* __restrict__ Alo) {
    __shared__ float sS[DD];
    __shared__ float sF[DD];
    int n = blockIdx.x;
    int tid = threadIdx.x;
    if (tid < DD) sF[tid] = F[n * DD + tid];
    if (tid < DD / 4) {
        float4 acc = make_float4(0.f, 0.f, 0.f, 0.f);
        int b = g_eoff[n];
        int e = g_eoff[n + 1];
        for (int i = b; i < e; i++) {
            int s = g_esrc[i];
            float4 v = *(const float4*)(proj + (size_t)s * DD + tid * 4);
            acc.x += v.x; acc.y += v.y; acc.z += v.z; acc.w += v.w;
        }
        *(float4*)&sS[tid * 4] = acc;
    }
    __syncthreads();
    if (tid < DD) {
        int b = g_rowptr[tid];
        int e = g_rowptr[tid + 1];
        float acc = 0.f;
        for (int t = b; t < e; t++)
            acc += g_Cs[t] * sS[g_Is[t]] * sF[g_Js[t]];
        __nv_bfloat16 h = __float2bfloat16(acc);
        Ahi[n * DD + tid] = h;
        Alo[n * DD + tid] = __float2bfloat16(acc - __bfloat162float(h));
    }
}

// ---------------- warp-MMA (mma.sync bf16) split GEMM, BK=64, frag pipelined -
// C[M,N] = A[M,K] @ B[N,K]^T via AhBh + AhBl + AlBh  (fp32 accumulate)
// CTA 128x64, 8 warps 4x2, warp tile 32x32, BK=64 (4 k16 steps/chunk),
// 2-stage cp.async, ldmatrix frags DOUBLE-BUFFERED across ksteps.
#define MMA16816(c, a, b)                                                     \
    asm volatile(                                                             \
        "mma.sync.aligned.m16n8k16.row.col.f32.bf16.bf16.f32 "                \
        "{%0,%1,%2,%3},{%4,%5,%6,%7},{%8,%9},{%0,%1,%2,%3};"                  \
        : "+f"((c)[0]), "+f"((c)[1]), "+f"((c)[2]), "+f"((c)[3])              \
        : "r"((a)[0]), "r"((a)[1]), "r"((a)[2]), "r"((a)[3]),                 \
          "r"((b)[0]), "r"((b)[1]))

#define LDSM4(r0, r1, r2, r3, addr)                                           \
    asm volatile("ldmatrix.sync.aligned.m8n8.x4.shared.b16 {%0,%1,%2,%3}, [%4];" \
                 : "=r"(r0), "=r"(r1), "=r"(r2), "=r"(r3) : "r"(addr))

#define CPASYNC16(saddr, gaddr, sz)                                           \
    asm volatile("cp.async.cg.shared.global [%0], [%1], 16, %2;"              \
                 :: "r"(saddr), "l"(gaddr), "r"(sz) : "memory")

#define ROWB        144u
#define A_PLANE     18432u      /* 128 * 144 */
#define B_OFF       36864u      /* 2 * A_PLANE */
#define B_PLANE     9216u       /* 64 * 144 */
#define BUF_BYTES   55296u      /* B_OFF + 2*B_PLANE */
#define NSTAGE      2

__device__ __forceinline__ uint32_t smem_u32(const void* p) {
    uint32_t a;
    asm("{ .reg .u64 t; cvta.to.shared.u64 t, %1; cvt.u32.u64 %0, t; }"
        : "=r"(a) : "l"(p));
    return a;
}

// load one kstep's fragments into buffer BUF
#define LOAD_FRAGS(BUF, KS)                                                   \
    do {                                                                      \
        _Pragma("unroll")                                                     \
        for (int mi = 0; mi < 2; mi++) {                                      \
            uint32_t row = (uint32_t)(wm * 32 + mi * 16 + lm01 * 8 + lr);     \
            uint32_t col = (uint32_t)((KS) + lm23 * 8);                       \
            uint32_t off = row * ROWB + col * 2u;                             \
            LDSM4(ah[BUF][mi][0], ah[BUF][mi][1], ah[BUF][mi][2],             \
                  ah[BUF][mi][3], abase + off);                               \
            LDSM4(al[BUF][mi][0], al[BUF][mi][1], al[BUF][mi][2],             \
                  al[BUF][mi][3], abase + A_PLANE + off);                     \
        }                                                                     \
        _Pragma("unroll")                                                     \
        for (int ng = 0; ng < 2; ng++) {                                      \
            uint32_t row = (uint32_t)(wn * 32 + ng * 16 + lm23 * 8 + lr);     \
            uint32_t col = (uint32_t)((KS) + lm01 * 8);                       \
            uint32_t off = row * ROWB + col * 2u;                             \
            LDSM4(bh[BUF][2 * ng][0], bh[BUF][2 * ng][1],                     \
                  bh[BUF][2 * ng + 1][0], bh[BUF][2 * ng + 1][1],             \
                  bbase + off);                                               \
            LDSM4(bl[BUF][2 * ng][0], bl[BUF][2 * ng][1],                     \
                  bl[BUF][2 * ng + 1][0], bl[BUF][2 * ng + 1][1],             \
                  bbase + B_PLANE + off);                                     \
        }                                                                     \
    } while (0)

template <int ACT, int SPLIT_OUT>
__global__ __launch_bounds__(256, 2) void hmma_gemm(
    const __nv_bfloat16* __restrict__ Ah, const __nv_bfloat16* __restrict__ Al,
    const __nv_bfloat16* __restrict__ Bh, const __nv_bfloat16* __restrict__ Bl,
    const float* __restrict__ bias,
    float* __restrict__ Cf,
    __nv_bfloat16* __restrict__ Chi, __nv_bfloat16* __restrict__ Clo,
    int M, int N, int K)
{
    extern __shared__ char smem[];
    uint32_t sbase = smem_u32(smem);

    int tid = threadIdx.x;
    int wid = tid >> 5;
    int lane = tid & 31;
    int g = lane >> 2;
    int tg = lane & 3;
    int wm = wid >> 1;
    int wn = wid & 1;
    int m0 = blockIdx.x * 128;
    int n0 = blockIdx.y * 64;

    int lr = lane & 7;
    int lm01 = (lane >> 3) & 1;
    int lm23 = lane >> 4;

    float acc[2][4][4];
#pragma unroll
    for (int mi = 0; mi < 2; mi++)
#pragma unroll
        for (int ni = 0; ni < 4; ni++)
#pragma unroll
            for (int q = 0; q < 4; q++) acc[mi][ni][q] = 0.f;

    int nkc = (K + 63) >> 6;

    auto issue_chunk = [&](int c) {
        int kc = c << 6;
        uint32_t bufb = sbase + (uint32_t)(c & 1) * BUF_BYTES;
#pragma unroll
        for (int r = 0; r < 8; ++r) {
            int i = tid + (r << 8);
            int plane = i >> 10;
            int row = (i >> 3) & 127;
            int seg = i & 7;
            int gm = m0 + row;
            int k = kc + seg * 8;
            const __nv_bfloat16* src = (plane ? Al : Ah) + (size_t)gm * K + k;
            uint32_t dst = bufb + (uint32_t)plane * A_PLANE + (uint32_t)row * ROWB
                           + (uint32_t)seg * 16u;
            uint32_t sz = (gm < M && k < K) ? 16u : 0u;
            CPASYNC16(dst, src, sz);
        }
#pragma unroll
        for (int r = 0; r < 4; ++r) {
            int i = tid + (r << 8);
            int plane = i >> 9;
            int row = (i >> 3) & 63;
            int seg = i & 7;
            int gn = n0 + row;
            int k = kc + seg * 8;
            const __nv_bfloat16* src = (plane ? Bl : Bh) + (size_t)gn * K + k;
            uint32_t dst = bufb + B_OFF + (uint32_t)plane * B_PLANE
                           + (uint32_t)row * ROWB + (uint32_t)seg * 16u;
            uint32_t sz = (gn < N && k < K) ? 16u : 0u;
            CPASYNC16(dst, src, sz);
        }
        asm volatile("cp.async.commit_group;" ::: "memory");
    };

    issue_chunk(0);

    for (int c = 0; c < nkc; ++c) {
        if (c + 1 < nkc) {
            issue_chunk(c + 1);
            asm volatile("cp.async.wait_group 1;" ::: "memory");
        } else {
            asm volatile("cp.async.wait_group 0;" ::: "memory");
        }
        __syncthreads();

        uint32_t abase = sbase + (uint32_t)(c & 1) * BUF_BYTES;
        uint32_t bbase = abase + B_OFF;

        uint32_t ah[2][2][4], al[2][2][4], bh[2][4][2], bl[2][4][2];
        LOAD_FRAGS(0, 0);
#pragma unroll
        for (int ks16 = 0; ks16 < 4; ks16++) {
            const int cb = ks16 & 1;
            if (ks16 < 3) {
                const int nb = (ks16 + 1) & 1;
                switch (ks16) {   // constant KS for each unrolled iteration
                    case 0: LOAD_FRAGS(1, 16); break;
                    case 1: LOAD_FRAGS(0, 32); break;
                    default: LOAD_FRAGS(1, 48); break;
                }
                (void)nb;
            }
            // product-major: 8 independent MMAs per pass
#pragma unroll
            for (int mi = 0; mi < 2; mi++)
#pragma unroll
                for (int ni = 0; ni < 4; ni++)
                    MMA16816(acc[mi][ni], ah[cb][mi], bh[cb][ni]);
#pragma unroll
            for (int mi = 0; mi < 2; mi++)
#pragma unroll
                for (int ni = 0; ni < 4; ni++)
                    MMA16816(acc[mi][ni], ah[cb][mi], bl[cb][ni]);
#pragma unroll
            for (int mi = 0; mi < 2; mi++)
#pragma unroll
                for (int ni = 0; ni < 4; ni++)
                    MMA16816(acc[mi][ni], al[cb][mi], bh[cb][ni]);
        }
        __syncthreads();
    }

    // ---- epilogue ----
#pragma unroll
    for (int mi = 0; mi < 2; mi++) {
#pragma unroll
        for (int ni = 0; ni < 4; ni++) {
#pragma unroll
            for (int h = 0; h < 2; h++) {
                int gm = m0 + wm * 32 + mi * 16 + g + h * 8;
                if (gm >= M) continue;
#pragma unroll
                for (int q = 0; q < 2; q++) {
                    int gn = n0 + wn * 32 + ni * 8 + tg * 2 + q;
                    if (gn >= N) continue;
                    float v = acc[mi][ni][h * 2 + q];
                    if (bias) v += bias[gn];
                    if (ACT == 1) v = v / (1.f + expf(-v));
                    if (SPLIT_OUT == 1) {
                        __nv_bfloat16 hh = __float2bfloat16(v);
                        Chi[(size_t)gm * N + gn] = hh;
                        Clo[(size_t)gm * N + gn] =
                            __float2bfloat16(v - __bfloat162float(hh));
                    } else {
                        Cf[(size_t)gm * N + gn] = v;
                    }
                }
            }
        }
    }
}

// ---------------- residual + LayerNorm (shuffle reductions) ----------------
__global__ void ln_kernel(const float* __restrict__ F, const float* __restrict__ h2,
                          const float* __restrict__ gamma, const float* __restrict__ beta,
                          float* __restrict__ out) {
    __shared__ float wred[8];
    int n = blockIdx.x;
    int tid = threadIdx.x;
    int lane = tid & 31;
    int wid = tid >> 5;
    float x = (tid < DD) ? (F[n * DD + tid] + h2[n * DD + tid]) : 0.f;

    float s = x;
#pragma unroll
    for (int o = 16; o > 0; o >>= 1) s += __shfl_xor_sync(0xFFFFFFFFu, s, o);
    if (lane == 0) wred[wid] = s;
    __syncthreads();
    float mu = 0.f;
#pragma unroll
    for (int i = 0; i < 8; i++) mu += wred[i];
    mu *= (1.f / DD);
    __syncthreads();

    float xc = (tid < DD) ? (x - mu) : 0.f;
    float s2 = xc * xc;
#pragma unroll
    for (int o = 16; o > 0; o >>= 1) s2 += __shfl_xor_sync(0xFFFFFFFFu, s2, o);
    if (lane == 0) wred[wid] = s2;
    __syncthreads();
    float var = 0.f;
#pragma unroll
    for (int i = 0; i < 8; i++) var += wred[i];
    var *= (1.f / DD);
    float r = rsqrtf(var + 1e-5f);
    if (tid < DD)
        out[n * DD + tid] = xc * r * gamma[tid] + beta[tid];
}

// ---------------- launcher ----------------
extern "C" void kernel_launch(void* const* d_in, const int* in_sizes, int n_in,
                              void* d_out, int out_size) {
    const float* features = (const float*)d_in[0];
    const int*   ei       = (const int*)d_in[1];
    const float* Wmsg     = (const float*)d_in[2];
    const float* W1       = (const float*)d_in[3];
    const float* b1       = (const float*)d_in[4];
    const float* W2       = (const float*)d_in[5];
    const float* b2       = (const float*)d_in[6];
    const float* gamma    = (const float*)d_in[7];
    const float* beta     = (const float*)d_in[8];
    const int*   Iv       = (const int*)d_in[9];
    const int*   Jv       = (const int*)d_in[10];
    const int*   Kv       = (const int*)d_in[11];
    const float* Cv       = (const float*)d_in[12];
    float* out = (float*)d_out;

    int N   = in_sizes[0] / DD;
    int E   = in_sizes[1] / 2;
    int nnz = in_sizes[9];

    float *p_proj, *p_h2;
    __nv_bfloat16 *p_fhi, *p_flo, *p_agghi, *p_agglo, *p_hidhi, *p_hidlo;
    __nv_bfloat16 *p_wmhi, *p_wmlo, *p_w1hi, *p_w1lo, *p_w2hi, *p_w2lo;
    cudaGetSymbolAddress((void**)&p_proj,  g_proj);
    cudaGetSymbolAddress((void**)&p_h2,    g_h2);
    cudaGetSymbolAddress((void**)&p_fhi,   g_fhi);
    cudaGetSymbolAddress((void**)&p_flo,   g_flo);
    cudaGetSymbolAddress((void**)&p_agghi, g_agghi);
    cudaGetSymbolAddress((void**)&p_agglo, g_agglo);
    cudaGetSymbolAddress((void**)&p_hidhi, g_hidhi);
    cudaGetSymbolAddress((void**)&p_hidlo, g_hidlo);
    cudaGetSymbolAddress((void**)&p_wmhi,  g_wmhi);
    cudaGetSymbolAddress((void**)&p_wmlo,  g_wmlo);
    cudaGetSymbolAddress((void**)&p_w1hi,  g_w1hi);
    cudaGetSymbolAddress((void**)&p_w1lo,  g_w1lo);
    cudaGetSymbolAddress((void**)&p_w2hi,  g_w2hi);
    cudaGetSymbolAddress((void**)&p_w2lo,  g_w2lo);

    const int SMEM_SZ = NSTAGE * 55296;
    cudaFuncSetAttribute(hmma_gemm<0, 0>, cudaFuncAttributeMaxDynamicSharedMemorySize, SMEM_SZ);
    cudaFuncSetAttribute(hmma_gemm<1, 1>, cudaFuncAttributeMaxDynamicSharedMemorySize, SMEM_SZ);

    // #1: features split + zero degree counters
    prep_feat_kernel<<<512, 256>>>(features, p_fhi, p_flo, N * DD, N);
    // #2: weight splits
    prep_w_kernel<<<256, 256>>>(Wmsg, W1, W2, p_wmhi, p_wmlo,
                                p_w1hi, p_w1lo, p_w2hi, p_w2lo);
    // #3: structure-constant CSR
    build_csr_fast<<<(nnz + 255) / 256, 256>>>(Iv, Jv, Kv, Cv, nnz);

    int mtiles = (N + 127) / 128;

    // #4 (profiled): proj = features @ Wmsg^T
    hmma_gemm<0, 0><<<dim3(mtiles, (DD + 63) / 64), 256, SMEM_SZ>>>(
        p_fhi, p_flo, p_wmhi, p_wmlo, nullptr, p_proj, nullptr, nullptr, N, DD, DD);

    // #5-#7: edge CSR (histogram, scan, fill)
    edge_count_kernel<<<(E + 255) / 256, 256>>>(ei, E);
    edge_scan_kernel<<<1, 256>>>(N);
    edge_fill_kernel<<<(E + 255) / 256, 256>>>(ei, E);

    // #8: fused segment-sum gather + Lie bracket, emits bf16 split
    gather_bracket_kernel<<<N, 256>>>(p_proj, features, p_agghi, p_agglo);

    // #9: hidden = silu(agg @ W1^T + b1), pre-split
    hmma_gemm<1, 1><<<dim3(mtiles, (HH + 63) / 64), 256, SMEM_SZ>>>(
        p_agghi, p_agglo, p_w1hi, p_w1lo, b1, nullptr, p_hidhi, p_hidlo, N, HH, DD);

    // #10: h2 = hidden @ W2^T + b2
    hmma_gemm<0, 0><<<dim3(mtiles, (DD + 63) / 64), 256, SMEM_SZ>>>(
        p_hidhi, p_hidlo, p_w2hi, p_w2lo, b2, p_h2, nullptr, nullptr, N, DD, HH);

    // #11: out = LayerNorm(features + h2)
    ln_kernel<<<N, 256>>>(features, p_h2, gamma, beta, out);
}

// round 12
// speedup vs baseline: 1.1612x; 1.1612x over previous
#include <cuda_runtime.h>
#include <cuda_bf16.h>
#include <math.h>
#include <stdint.h>

#define DD   248
#define HH   512
#define NMAX 10000
#define NNZMAX 4096

// ---------------- scratch (device globals; no allocs allowed) ----------------
__device__ float g_proj[NMAX * DD];
__device__ float g_S[NMAX * DD];
__device__ float g_h2[NMAX * DD];
__device__ __align__(16) __nv_bfloat16 g_fhi[NMAX * DD];
__device__ __align__(16) __nv_bfloat16 g_flo[NMAX * DD];
__device__ __align__(16) __nv_bfloat16 g_agghi[NMAX * DD];
__device__ __align__(16) __nv_bfloat16 g_agglo[NMAX * DD];
__device__ __align__(16) __nv_bfloat16 g_hidhi[NMAX * HH];
__device__ __align__(16) __nv_bfloat16 g_hidlo[NMAX * HH];
__device__ __align__(16) __nv_bfloat16 g_wmhi[DD * DD];
__device__ __align__(16) __nv_bfloat16 g_wmlo[DD * DD];
__device__ __align__(16) __nv_bfloat16 g_w1hi[HH * DD];
__device__ __align__(16) __nv_bfloat16 g_w1lo[HH * DD];
__device__ __align__(16) __nv_bfloat16 g_w2hi[DD * HH];
__device__ __align__(16) __nv_bfloat16 g_w2lo[DD * HH];
__device__ int   g_rowptr[DD + 1];
__device__ int   g_Is[NNZMAX];
__device__ int   g_Js[NNZMAX];
__device__ float g_Cs[NNZMAX];

// ---------------- splits ----------------
__device__ __forceinline__ void split1(const float* __restrict__ x,
                                       __nv_bfloat16* __restrict__ hi,
                                       __nv_bfloat16* __restrict__ lo, int i) {
    float v = x[i];
    __nv_bfloat16 h = __float2bfloat16(v);
    hi[i] = h;
    lo[i] = __float2bfloat16(v - __bfloat162float(h));
}

// launch #1: features split + zero S
__global__ void prep_feat_kernel(const float* __restrict__ F,
                                 __nv_bfloat16* __restrict__ fhi,
                                 __nv_bfloat16* __restrict__ flo,
                                 float* __restrict__ S, int nfeat) {
    int i = blockIdx.x * blockDim.x + threadIdx.x;
    int stride = gridDim.x * blockDim.x;
    for (; i < nfeat; i += stride) {
        split1(F, fhi, flo, i);
        S[i] = 0.f;
    }
}

// launch #2: all weight splits
__global__ void prep_w_kernel(const float* __restrict__ Wmsg,
                              const float* __restrict__ W1,
                              const float* __restrict__ W2,
                              __nv_bfloat16* __restrict__ wmhi, __nv_bfloat16* __restrict__ wmlo,
                              __nv_bfloat16* __restrict__ w1hi, __nv_bfloat16* __restrict__ w1lo,
                              __nv_bfloat16* __restrict__ w2hi, __nv_bfloat16* __restrict__ w2lo) {
    const int s1 = DD * DD;
    const int s2 = HH * DD;
    const int s3 = DD * HH;
    int total = s1 + s2 + s3;
    int i = blockIdx.x * blockDim.x + threadIdx.x;
    int stride = gridDim.x * blockDim.x;
    for (; i < total; i += stride) {
        if (i < s1)            split1(Wmsg, wmhi, wmlo, i);
        else if (i < s1 + s2)  split1(W1, w1hi, w1lo, i - s1);
        else                   split1(W2, w2hi, w2lo, i - s1 - s2);
    }
}

// launch #3: deterministic parallel CSR build (stable rank-by-scan).
__global__ void build_csr_fast(const int* __restrict__ Iv, const int* __restrict__ Jv,
                               const int* __restrict__ Kv, const float* __restrict__ Cv,
                               int nnz) {
    __shared__ int sK[NNZMAX];
    __shared__ int cnt[DD];
    int tid = threadIdx.x;
    for (int t = tid; t < nnz; t += blockDim.x) sK[t] = Kv[t];
    for (int k = tid; k < DD; k += blockDim.x) cnt[k] = 0;
    __syncthreads();
    for (int t = tid; t < nnz; t += blockDim.x) atomicAdd(&cnt[sK[t]], 1);
    __syncthreads();
    __shared__ int off[DD + 1];
    if (tid == 0) {
        int s = 0;
        for (int k = 0; k < DD; k++) { off[k] = s; s += cnt[k]; }
        off[DD] = s;
    }
    __syncthreads();
    if (blockIdx.x == 0)
        for (int k = tid; k <= DD; k += blockDim.x) g_rowptr[k] = off[k];
    int t = blockIdx.x * blockDim.x + tid;
    if (t < nnz) {
        int k = sK[t];
        int rank = 0;
        for (int t2 = 0; t2 < t; ++t2) rank += (sK[t2] == k);
        int pos = off[k] + rank;
        g_Is[pos] = Iv[t];
        g_Js[pos] = Jv[t];
        g_Cs[pos] = Cv[t];
    }
}

// S[tgt[e]] += proj[src[e]] : 64 threads per edge, float4 vectorized atomics
__global__ void scatter_edges_kernel(const int* __restrict__ ei,
                                     const float* __restrict__ proj,
                                     float* __restrict__ S, int E) {
    int gid = blockIdx.x * blockDim.x + threadIdx.x;
    int e = gid >> 6;
    int c = gid & 63;
    if (e >= E || c >= DD / 4) return;
    int s = ei[e];
    int t = ei[E + e];
    float4 v = *(const float4*)(proj + (size_t)s * DD + c * 4);
#if __CUDA_ARCH__ >= 900
    atomicAdd((float4*)(S + (size_t)t * DD + c * 4), v);
#else
    float* p = S + (size_t)t * DD + c * 4;
    atomicAdd(p + 0, v.x); atomicAdd(p + 1, v.y);
    atomicAdd(p + 2, v.z); atomicAdd(p + 3, v.w);
#endif
}

// agg[n,k] = sum_t C_t * S[n,I_t] * f[n,J_t]; emits bf16 split directly
__global__ void bracket_kernel(const float* __restrict__ S, const float* __restrict__ F,
                               __nv_bfloat16* __restrict__ Ahi,
                               __nv_bfloat16* __restrict__ Alo) {
    __shared__ float sS[DD];
    __shared__ float sF[DD];
    int n = blockIdx.x;
    int tid = threadIdx.x;
    if (tid < DD) {
        sS[tid] = S[n * DD + tid];
        sF[tid] = F[n * DD + tid];
    }
    __syncthreads();
    if (tid < DD) {
        int b = g_rowptr[tid];
        int e = g_rowptr[tid + 1];
        float acc = 0.f;
        for (int t = b; t < e; t++)
            acc += g_Cs[t] * sS[g_Is[t]] * sF[g_Js[t]];
        __nv_bfloat16 h = __float2bfloat16(acc);
        Ahi[n * DD + tid] = h;
        Alo[n * DD + tid] = __float2bfloat16(acc - __bfloat162float(h));
    }
}

// fast SiLU: x * sigmoid(x) = 0.5*x*(1 + tanh(x/2)) using MUFU tanh.approx
__device__ __forceinline__ float fast_silu(float v) {
    float t;
    asm("tanh.approx.f32 %0, %1;" : "=f"(t) : "f"(v * 0.5f));
    return 0.5f * v * (1.0f + t);
}

// ---------------- warp-MMA (mma.sync bf16) split GEMM, BK=64 --------
// C[M,N] = A[M,K] @ B[N,K]^T via AhBh + AhBl + AlBh  (fp32 accumulate)
// CTA 128x64, 8 warps 4x2, warp tile 32x32, BK=64 (4 k16 steps/chunk),
// 2-stage cp.async, ldmatrix frags, product-major MMA order.
// Packed bf16x2/float2 epilogue stores; SiLU via tanh.approx.
#define MMA16816(c, a, b)                                                     \
    asm volatile(                                                             \
        "mma.sync.aligned.m16n8k16.row.col.f32.bf16.bf16.f32 "                \
        "{%0,%1,%2,%3},{%4,%5,%6,%7},{%8,%9},{%0,%1,%2,%3};"                  \
        : "+f"((c)[0]), "+f"((c)[1]), "+f"((c)[2]), "+f"((c)[3])              \
        : "r"((a)[0]), "r"((a)[1]), "r"((a)[2]), "r"((a)[3]),                 \
          "r"((b)[0]), "r"((b)[1]))

#define LDSM4(r0, r1, r2, r3, addr)                                           \
    asm volatile("ldmatrix.sync.aligned.m8n8.x4.shared.b16 {%0,%1,%2,%3}, [%4];" \
                 : "=r"(r0), "=r"(r1), "=r"(r2), "=r"(r3) : "r"(addr))

#define CPASYNC16(saddr, gaddr, sz)                                           \
    asm volatile("cp.async.cg.shared.global [%0], [%1], 16, %2;"              \
                 :: "r"(saddr), "l"(gaddr), "r"(sz) : "memory")

#define ROWB        144u
#define A_PLANE     18432u      /* 128 * 144 */
#define B_OFF       36864u      /* 2 * A_PLANE */
#define B_PLANE     9216u       /* 64 * 144 */
#define BUF_BYTES   55296u      /* B_OFF + 2*B_PLANE */
#define NSTAGE      2

__device__ __forceinline__ uint32_t smem_u32(const void* p) {
    uint32_t a;
    asm("{ .reg .u64 t; cvta.to.shared.u64 t, %1; cvt.u32.u64 %0, t; }"
        : "=r"(a) : "l"(p));
    return a;
}

template <int ACT, int SPLIT_OUT>
__global__ __launch_bounds__(256) void hmma_gemm(
    const __nv_bfloat16* __restrict__ Ah, const __nv_bfloat16* __restrict__ Al,
    const __nv_bfloat16* __restrict__ Bh, const __nv_bfloat16* __restrict__ Bl,
    const float* __restrict__ bias,
    float* __restrict__ Cf,
    __nv_bfloat16* __restrict__ Chi, __nv_bfloat16* __restrict__ Clo,
    int M, int N, int K)
{
    extern __shared__ char smem[];
    uint32_t sbase = smem_u32(smem);

    int tid = threadIdx.x;
    int wid = tid >> 5;
    int lane = tid & 31;
    int g = lane >> 2;
    int tg = lane & 3;
    int wm = wid >> 1;
    int wn = wid & 1;
    int m0 = blockIdx.x * 128;
    int n0 = blockIdx.y * 64;

    int lr = lane & 7;
    int lm01 = (lane >> 3) & 1;
    int lm23 = lane >> 4;

    float acc[2][4][4];
#pragma unroll
    for (int mi = 0; mi < 2; mi++)
#pragma unroll
        for (int ni = 0; ni < 4; ni++)
#pragma unroll
            for (int q = 0; q < 4; q++) acc[mi][ni][q] = 0.f;

    int nkc = (K + 63) >> 6;

    auto issue_chunk = [&](int c) {
        int kc = c << 6;
        uint32_t bufb = sbase + (uint32_t)(c & 1) * BUF_BYTES;
#pragma unroll
        for (int r = 0; r < 8; ++r) {
            int i = tid + (r << 8);
            int plane = i >> 10;
            int row = (i >> 3) & 127;
            int seg = i & 7;
            int gm = m0 + row;
            int k = kc + seg * 8;
            const __nv_bfloat16* src = (plane ? Al : Ah) + (size_t)gm * K + k;
            uint32_t dst = bufb + (uint32_t)plane * A_PLANE + (uint32_t)row * ROWB
                           + (uint32_t)seg * 16u;
            uint32_t sz = (gm < M && k < K) ? 16u : 0u;
            CPASYNC16(dst, src, sz);
        }
#pragma unroll
        for (int r = 0; r < 4; ++r) {
            int i = tid + (r << 8);
            int plane = i >> 9;
            int row = (i >> 3) & 63;
            int seg = i & 7;
            int gn = n0 + row;
            int k = kc + seg * 8;
            const __nv_bfloat16* src = (plane ? Bl : Bh) + (size_t)gn * K + k;
            uint32_t dst = bufb + B_OFF + (uint32_t)plane * B_PLANE
                           + (uint32_t)row * ROWB + (uint32_t)seg * 16u;
            uint32_t sz = (gn < N && k < K) ? 16u : 0u;
            CPASYNC16(dst, src, sz);
        }
        asm volatile("cp.async.commit_group;" ::: "memory");
    };

    issue_chunk(0);

    for (int c = 0; c < nkc; ++c) {
        if (c + 1 < nkc) {
            issue_chunk(c + 1);
            asm volatile("cp.async.wait_group 1;" ::: "memory");
        } else {
            asm volatile("cp.async.wait_group 0;" ::: "memory");
        }
        __syncthreads();

        uint32_t abase = sbase + (uint32_t)(c & 1) * BUF_BYTES;
        uint32_t bbase = abase + B_OFF;
#pragma unroll
        for (int ks = 0; ks < 64; ks += 16) {
            uint32_t ah[2][4], al[2][4], bh[4][2], bl[4][2];
#pragma unroll
            for (int mi = 0; mi < 2; mi++) {
                uint32_t row = (uint32_t)(wm * 32 + mi * 16 + lm01 * 8 + lr);
                uint32_t col = (uint32_t)(ks + lm23 * 8);
                uint32_t off = row * ROWB + col * 2u;
                LDSM4(ah[mi][0], ah[mi][1], ah[mi][2], ah[mi][3], abase + off);
                LDSM4(al[mi][0], al[mi][1], al[mi][2], al[mi][3],
                      abase + A_PLANE + off);
            }
#pragma unroll
            for (int ng = 0; ng < 2; ng++) {
                uint32_t row = (uint32_t)(wn * 32 + ng * 16 + lm23 * 8 + lr);
                uint32_t col = (uint32_t)(ks + lm01 * 8);
                uint32_t off = row * ROWB + col * 2u;
                LDSM4(bh[2 * ng][0], bh[2 * ng][1], bh[2 * ng + 1][0],
                      bh[2 * ng + 1][1], bbase + off);
                LDSM4(bl[2 * ng][0], bl[2 * ng][1], bl[2 * ng + 1][0],
                      bl[2 * ng + 1][1], bbase + B_PLANE + off);
            }
#pragma unroll
            for (int mi = 0; mi < 2; mi++)
#pragma unroll
                for (int ni = 0; ni < 4; ni++)
                    MMA16816(acc[mi][ni], ah[mi], bh[ni]);
#pragma unroll
            for (int mi = 0; mi < 2; mi++)
#pragma unroll
                for (int ni = 0; ni < 4; ni++)
                    MMA16816(acc[mi][ni], ah[mi], bl[ni]);
#pragma unroll
            for (int mi = 0; mi < 2; mi++)
#pragma unroll
                for (int ni = 0; ni < 4; ni++)
                    MMA16816(acc[mi][ni], al[mi], bh[ni]);
        }
        __syncthreads();
    }

    // ---- epilogue: paired (q=0,1) stores, fast SiLU ----
#pragma unroll
    for (int mi = 0; mi < 2; mi++) {
#pragma unroll
        for (int ni = 0; ni < 4; ni++) {
#pragma unroll
            for (int h = 0; h < 2; h++) {
                int gm = m0 + wm * 32 + mi * 16 + g + h * 8;
                if (gm >= M) continue;
                int gn0 = n0 + wn * 32 + ni * 8 + tg * 2;
                if (gn0 >= N) continue;   // N even, gn0 even -> gn0+1 < N
                float v0 = acc[mi][ni][h * 2 + 0];
                float v1 = acc[mi][ni][h * 2 + 1];
                if (bias) { v0 += bias[gn0]; v1 += bias[gn0 + 1]; }
                if (ACT == 1) { v0 = fast_silu(v0); v1 = fast_silu(v1); }
                if (SPLIT_OUT == 1) {
                    __nv_bfloat16 h0 = __float2bfloat16(v0);
                    __nv_bfloat16 h1 = __float2bfloat16(v1);
                    __nv_bfloat162 hp; hp.x = h0; hp.y = h1;
                    *(__nv_bfloat162*)(Chi + (size_t)gm * N + gn0) = hp;
                    __nv_bfloat162 lp;
                    lp.x = __float2bfloat16(v0 - __bfloat162float(h0));
                    lp.y = __float2bfloat16(v1 - __bfloat162float(h1));
                    *(__nv_bfloat162*)(Clo + (size_t)gm * N + gn0) = lp;
                } else {
                    float2 fv = make_float2(v0, v1);
                    *(float2*)(Cf + (size_t)gm * N + gn0) = fv;
                }
            }
        }
    }
}

// ---------------- residual + LayerNorm (shuffle reductions) ----------------
__global__ void ln_kernel(const float* __restrict__ F, const float* __restrict__ h2,
                          const float* __restrict__ gamma, const float* __restrict__ beta,
                          float* __restrict__ out) {
    __shared__ float wred[8];
    int n = blockIdx.x;
    int tid = threadIdx.x;
    int lane = tid & 31;
    int wid = tid >> 5;
    float x = (tid < DD) ? (F[n * DD + tid] + h2[n * DD + tid]) : 0.f;

    float s = x;
#pragma unroll
    for (int o = 16; o > 0; o >>= 1) s += __shfl_xor_sync(0xFFFFFFFFu, s, o);
    if (lane == 0) wred[wid] = s;
    __syncthreads();
    float mu = 0.f;
#pragma unroll
    for (int i = 0; i < 8; i++) mu += wred[i];
    mu *= (1.f / DD);
    __syncthreads();

    float xc = (tid < DD) ? (x - mu) : 0.f;
    float s2 = xc * xc;
#pragma unroll
    for (int o = 16; o > 0; o >>= 1) s2 += __shfl_xor_sync(0xFFFFFFFFu, s2, o);
    if (lane == 0) wred[wid] = s2;
    __syncthreads();
    float var = 0.f;
#pragma unroll
    for (int i = 0; i < 8; i++) var += wred[i];
    var *= (1.f / DD);
    float r = rsqrtf(var + 1e-5f);
    if (tid < DD)
        out[n * DD + tid] = xc * r * gamma[tid] + beta[tid];
}

// ---------------- launcher ----------------
extern "C" void kernel_launch(void* const* d_in, const int* in_sizes, int n_in,
                              void* d_out, int out_size) {
    const float* features = (const float*)d_in[0];
    const int*   ei       = (const int*)d_in[1];
    const float* Wmsg     = (const float*)d_in[2];
    const float* W1       = (const float*)d_in[3];
    const float* b1       = (const float*)d_in[4];
    const float* W2       = (const float*)d_in[5];
    const float* b2       = (const float*)d_in[6];
    const float* gamma    = (const float*)d_in[7];
    const float* beta     = (const float*)d_in[8];
    const int*   Iv       = (const int*)d_in[9];
    const int*   Jv       = (const int*)d_in[10];
    const int*   Kv       = (const int*)d_in[11];
    const float* Cv       = (const float*)d_in[12];
    float* out = (float*)d_out;

    int N   = in_sizes[0] / DD;
    int E   = in_sizes[1] / 2;
    int nnz = in_sizes[9];

    float *p_proj, *p_S, *p_h2;
    __nv_bfloat16 *p_fhi, *p_flo, *p_agghi, *p_agglo, *p_hidhi, *p_hidlo;
    __nv_bfloat16 *p_wmhi, *p_wmlo, *p_w1hi, *p_w1lo, *p_w2hi, *p_w2lo;
    cudaGetSymbolAddress((void**)&p_proj,  g_proj);
    cudaGetSymbolAddress((void**)&p_S,     g_S);
    cudaGetSymbolAddress((void**)&p_h2,    g_h2);
    cudaGetSymbolAddress((void**)&p_fhi,   g_fhi);
    cudaGetSymbolAddress((void**)&p_flo,   g_flo);
    cudaGetSymbolAddress((void**)&p_agghi, g_agghi);
    cudaGetSymbolAddress((void**)&p_agglo, g_agglo);
    cudaGetSymbolAddress((void**)&p_hidhi, g_hidhi);
    cudaGetSymbolAddress((void**)&p_hidlo, g_hidlo);
    cudaGetSymbolAddress((void**)&p_wmhi,  g_wmhi);
    cudaGetSymbolAddress((void**)&p_wmlo,  g_wmlo);
    cudaGetSymbolAddress((void**)&p_w1hi,  g_w1hi);
    cudaGetSymbolAddress((void**)&p_w1lo,  g_w1lo);
    cudaGetSymbolAddress((void**)&p_w2hi,  g_w2hi);
    cudaGetSymbolAddress((void**)&p_w2lo,  g_w2lo);

    const int SMEM_SZ = NSTAGE * 55296;
    cudaFuncSetAttribute(hmma_gemm<0, 0>, cudaFuncAttributeMaxDynamicSharedMemorySize, SMEM_SZ);
    cudaFuncSetAttribute(hmma_gemm<1, 1>, cudaFuncAttributeMaxDynamicSharedMemorySize, SMEM_SZ);

    // #1: features split + zero S
    prep_feat_kernel<<<512, 256>>>(features, p_fhi, p_flo, p_S, N * DD);
    // #2: weight splits
    prep_w_kernel<<<256, 256>>>(Wmsg, W1, W2, p_wmhi, p_wmlo,
                                p_w1hi, p_w1lo, p_w2hi, p_w2lo);
    // #3: structure-constant CSR
    build_csr_fast<<<(nnz + 255) / 256, 256>>>(Iv, Jv, Kv, Cv, nnz);

    int mtiles = (N + 127) / 128;

    // #4 (profiled): proj = features @ Wmsg^T
    hmma_gemm<0, 0><<<dim3(mtiles, (DD + 63) / 64), 256, SMEM_SZ>>>(
        p_fhi, p_flo, p_wmhi, p_wmlo, nullptr, p_proj, nullptr, nullptr, N, DD, DD);

    // #5: S[tgt] += proj[src]
    scatter_edges_kernel<<<(E * 64 + 255) / 256, 256>>>(ei, p_proj, p_S, E);

    // #6: agg = bracket(S, features), pre-split
    bracket_kernel<<<N, 256>>>(p_S, features, p_agghi, p_agglo);

    // #7: hidden = silu(agg @ W1^T + b1), pre-split
    hmma_gemm<1, 1><<<dim3(mtiles, (HH + 63) / 64), 256, SMEM_SZ>>>(
        p_agghi, p_agglo, p_w1hi, p_w1lo, b1, nullptr, p_hidhi, p_hidlo, N, HH, DD);

    // #8: h2 = hidden @ W2^T + b2
    hmma_gemm<0, 0><<<dim3(mtiles, (DD + 63) / 64), 256, SMEM_SZ>>>(
        p_hidhi, p_hidlo, p_w2hi, p_w2lo, b2, p_h2, nullptr, nullptr, N, DD, HH);

    // #9: out = LayerNorm(features + h2)
    ln_kernel<<<N, 256>>>(features, p_h2, gamma, beta, out);
}

// round 13
// speedup vs baseline: 1.1892x; 1.0241x over previous
#include <cuda_runtime.h>
#include <cuda_bf16.h>
#include <math.h>
#include <stdint.h>

#define DD   248
#define HH   512
#define NMAX 10000
#define NNZMAX 4096

// ---------------- scratch (device globals; no allocs allowed) ----------------
__device__ float g_proj[NMAX * DD];
__device__ float g_S[NMAX * DD];
__device__ float g_h2[NMAX * DD];
__device__ __align__(16) __nv_bfloat16 g_fhi[NMAX * DD];
__device__ __align__(16) __nv_bfloat16 g_flo[NMAX * DD];
__device__ __align__(16) __nv_bfloat16 g_agghi[NMAX * DD];
__device__ __align__(16) __nv_bfloat16 g_agglo[NMAX * DD];
__device__ __align__(16) __nv_bfloat16 g_hidhi[NMAX * HH];
__device__ __align__(16) __nv_bfloat16 g_hidlo[NMAX * HH];
__device__ __align__(16) __nv_bfloat16 g_wmhi[DD * DD];
__device__ __align__(16) __nv_bfloat16 g_wmlo[DD * DD];
__device__ __align__(16) __nv_bfloat16 g_w1hi[HH * DD];
__device__ __align__(16) __nv_bfloat16 g_w1lo[HH * DD];
__device__ __align__(16) __nv_bfloat16 g_w2hi[DD * HH];
__device__ __align__(16) __nv_bfloat16 g_w2lo[DD * HH];
__device__ int   g_rowptr[DD + 1];
__device__ int   g_Is[NNZMAX];
__device__ int   g_Js[NNZMAX];
__device__ float g_Cs[NNZMAX];

// ---------------- splits ----------------
__device__ __forceinline__ void split1(const float* __restrict__ x,
                                       __nv_bfloat16* __restrict__ hi,
                                       __nv_bfloat16* __restrict__ lo, int i) {
    float v = x[i];
    __nv_bfloat16 h = __float2bfloat16(v);
    hi[i] = h;
    lo[i] = __float2bfloat16(v - __bfloat162float(h));
}

// launch #1 (fused setup): blocks [0, csrBlocks) build the structure-constant
// CSR (stable rank-by-scan, deterministic); remaining blocks do all bf16
// splits + zero S in one grid-stride sweep.
__global__ void combo_prep_kernel(
    const float* __restrict__ F,
    const float* __restrict__ Wmsg,
    const float* __restrict__ W1,
    const float* __restrict__ W2,
    const int* __restrict__ Iv, const int* __restrict__ Jv,
    const int* __restrict__ Kv, const float* __restrict__ Cv,
    __nv_bfloat16* __restrict__ fhi, __nv_bfloat16* __restrict__ flo,
    __nv_bfloat16* __restrict__ wmhi, __nv_bfloat16* __restrict__ wmlo,
    __nv_bfloat16* __restrict__ w1hi, __nv_bfloat16* __restrict__ w1lo,
    __nv_bfloat16* __restrict__ w2hi, __nv_bfloat16* __restrict__ w2lo,
    float* __restrict__ S, int nfeat, int nnz, int csrBlocks)
{
    int tid = threadIdx.x;
    if (blockIdx.x < (unsigned)csrBlocks) {
        // ---- CSR path ----
        __shared__ int sK[NNZMAX];
        __shared__ int cnt[DD];
        __shared__ int off[DD + 1];
        for (int t = tid; t < nnz; t += blockDim.x) sK[t] = Kv[t];
        for (int k = tid; k < DD; k += blockDim.x) cnt[k] = 0;
        __syncthreads();
        for (int t = tid; t < nnz; t += blockDim.x) atomicAdd(&cnt[sK[t]], 1);
        __syncthreads();
        if (tid == 0) {
            int s = 0;
            for (int k = 0; k < DD; k++) { off[k] = s; s += cnt[k]; }
            off[DD] = s;
        }
        __syncthreads();
        if (blockIdx.x == 0)
            for (int k = tid; k <= DD; k += blockDim.x) g_rowptr[k] = off[k];
        int t = blockIdx.x * blockDim.x + tid;
        if (t < nnz) {
            int k = sK[t];
            int rank = 0;
            for (int t2 = 0; t2 < t; ++t2) rank += (sK[t2] == k);
            int pos = off[k] + rank;
            g_Is[pos] = Iv[t];
            g_Js[pos] = Jv[t];
            g_Cs[pos] = Cv[t];
        }
    } else {
        // ---- prep path ----
        const int s1 = DD * DD;
        const int s2 = HH * DD;
        const int s3 = DD * HH;
        int total = nfeat + s1 + s2 + s3;
        int nblocks = gridDim.x - csrBlocks;
        int i = (blockIdx.x - csrBlocks) * blockDim.x + tid;
        int stride = nblocks * blockDim.x;
        for (; i < total; i += stride) {
            if (i < nfeat) {
                split1(F, fhi, flo, i);
                S[i] = 0.f;
            } else if (i < nfeat + s1) {
                split1(Wmsg, wmhi, wmlo, i - nfeat);
            } else if (i < nfeat + s1 + s2) {
                split1(W1, w1hi, w1lo, i - nfeat - s1);
            } else {
                split1(W2, w2hi, w2lo, i - nfeat - s1 - s2);
            }
        }
    }
}

// S[tgt[e]] += proj[src[e]] : 4 edges per block, indices cached in smem,
// 64 threads per edge, float4 vectorized atomics.
__global__ void scatter_edges_kernel(const int* __restrict__ ei,
                                     const float* __restrict__ proj,
                                     float* __restrict__ S, int E) {
    __shared__ int sidx[8];
    int e0 = blockIdx.x * 4;
    int tid = threadIdx.x;
    if (tid < 8) {
        int slot = tid >> 1;
        int e = e0 + slot;
        int v = -1;
        if (e < E) v = (tid & 1) ? ei[E + e] : ei[e];
        sidx[tid] = v;
    }
    __syncthreads();
    int grp = tid >> 6;       // 0..3 edge slot
    int c = tid & 63;         // float4 column
    int e = e0 + grp;
    if (e >= E || c >= DD / 4) return;
    int s = sidx[2 * grp];
    int t = sidx[2 * grp + 1];
    float4 v = *(const float4*)(proj + (size_t)s * DD + c * 4);
#if __CUDA_ARCH__ >= 900
    atomicAdd((float4*)(S + (size_t)t * DD + c * 4), v);
#else
    float* p = S + (size_t)t * DD + c * 4;
    atomicAdd(p + 0, v.x); atomicAdd(p + 1, v.y);
    atomicAdd(p + 2, v.z); atomicAdd(p + 3, v.w);
#endif
}

// agg[n,k] = sum_t C_t * S[n,I_t] * f[n,J_t]; emits bf16 split directly
__global__ void bracket_kernel(const float* __restrict__ S, const float* __restrict__ F,
                               __nv_bfloat16* __restrict__ Ahi,
                               __nv_bfloat16* __restrict__ Alo) {
    __shared__ float sS[DD];
    __shared__ float sF[DD];
    int n = blockIdx.x;
    int tid = threadIdx.x;
    if (tid < DD) {
        sS[tid] = S[n * DD + tid];
        sF[tid] = F[n * DD + tid];
    }
    __syncthreads();
    if (tid < DD) {
        int b = g_rowptr[tid];
        int e = g_rowptr[tid + 1];
        float acc = 0.f;
        for (int t = b; t < e; t++)
            acc += g_Cs[t] * sS[g_Is[t]] * sF[g_Js[t]];
        __nv_bfloat16 h = __float2bfloat16(acc);
        Ahi[n * DD + tid] = h;
        Alo[n * DD + tid] = __float2bfloat16(acc - __bfloat162float(h));
    }
}

// fast SiLU: x * sigmoid(x) = 0.5*x*(1 + tanh(x/2)) using MUFU tanh.approx
__device__ __forceinline__ float fast_silu(float v) {
    float t;
    asm("tanh.approx.f32 %0, %1;" : "=f"(t) : "f"(v * 0.5f));
    return 0.5f * v * (1.0f + t);
}

// ---------------- warp-MMA (mma.sync bf16) split GEMM, BK=64 --------
#define MMA16816(c, a, b)                                                     \
    asm volatile(                                                             \
        "mma.sync.aligned.m16n8k16.row.col.f32.bf16.bf16.f32 "                \
        "{%0,%1,%2,%3},{%4,%5,%6,%7},{%8,%9},{%0,%1,%2,%3};"                  \
        : "+f"((c)[0]), "+f"((c)[1]), "+f"((c)[2]), "+f"((c)[3])              \
        : "r"((a)[0]), "r"((a)[1]), "r"((a)[2]), "r"((a)[3]),                 \
          "r"((b)[0]), "r"((b)[1]))

#define LDSM4(r0, r1, r2, r3, addr)                                           \
    asm volatile("ldmatrix.sync.aligned.m8n8.x4.shared.b16 {%0,%1,%2,%3}, [%4];" \
                 : "=r"(r0), "=r"(r1), "=r"(r2), "=r"(r3) : "r"(addr))

#define CPASYNC16(saddr, gaddr, sz)                                           \
    asm volatile("cp.async.cg.shared.global [%0], [%1], 16, %2;"              \
                 :: "r"(saddr), "l"(gaddr), "r"(sz) : "memory")

#define ROWB        144u
#define A_PLANE     18432u
#define B_OFF       36864u
#define B_PLANE     9216u
#define BUF_BYTES   55296u
#define NSTAGE      2

__device__ __forceinline__ uint32_t smem_u32(const void* p) {
    uint32_t a;
    asm("{ .reg .u64 t; cvta.to.shared.u64 t, %1; cvt.u32.u64 %0, t; }"
        : "=r"(a) : "l"(p));
    return a;
}

template <int ACT, int SPLIT_OUT>
__global__ __launch_bounds__(256) void hmma_gemm(
    const __nv_bfloat16* __restrict__ Ah, const __nv_bfloat16* __restrict__ Al,
    const __nv_bfloat16* __restrict__ Bh, const __nv_bfloat16* __restrict__ Bl,
    const float* __restrict__ bias,
    float* __restrict__ Cf,
    __nv_bfloat16* __restrict__ Chi, __nv_bfloat16* __restrict__ Clo,
    int M, int N, int K)
{
    extern __shared__ char smem[];
    uint32_t sbase = smem_u32(smem);

    int tid = threadIdx.x;
    int wid = tid >> 5;
    int lane = tid & 31;
    int g = lane >> 2;
    int tg = lane & 3;
    int wm = wid >> 1;
    int wn = wid & 1;
    int m0 = blockIdx.x * 128;
    int n0 = blockIdx.y * 64;

    int lr = lane & 7;
    int lm01 = (lane >> 3) & 1;
    int lm23 = lane >> 4;

    float acc[2][4][4];
#pragma unroll
    for (int mi = 0; mi < 2; mi++)
#pragma unroll
        for (int ni = 0; ni < 4; ni++)
#pragma unroll
            for (int q = 0; q < 4; q++) acc[mi][ni][q] = 0.f;

    int nkc = (K + 63) >> 6;

    auto issue_chunk = [&](int c) {
        int kc = c << 6;
        uint32_t bufb = sbase + (uint32_t)(c & 1) * BUF_BYTES;
#pragma unroll
        for (int r = 0; r < 8; ++r) {
            int i = tid + (r << 8);
            int plane = i >> 10;
            int row = (i >> 3) & 127;
            int seg = i & 7;
            int gm = m0 + row;
            int k = kc + seg * 8;
            const __nv_bfloat16* src = (plane ? Al : Ah) + (size_t)gm * K + k;
            uint32_t dst = bufb + (uint32_t)plane * A_PLANE + (uint32_t)row * ROWB
                           + (uint32_t)seg * 16u;
            uint32_t sz = (gm < M && k < K) ? 16u : 0u;
            CPASYNC16(dst, src, sz);
        }
#pragma unroll
        for (int r = 0; r < 4; ++r) {
            int i = tid + (r << 8);
            int plane = i >> 9;
            int row = (i >> 3) & 63;
            int seg = i & 7;
            int gn = n0 + row;
            int k = kc + seg * 8;
            const __nv_bfloat16* src = (plane ? Bl : Bh) + (size_t)gn * K + k;
            uint32_t dst = bufb + B_OFF + (uint32_t)plane * B_PLANE
                           + (uint32_t)row * ROWB + (uint32_t)seg * 16u;
            uint32_t sz = (gn < N && k < K) ? 16u : 0u;
            CPASYNC16(dst, src, sz);
        }
        asm volatile("cp.async.commit_group;" ::: "memory");
    };

    issue_chunk(0);

    for (int c = 0; c < nkc; ++c) {
        if (c + 1 < nkc) {
            issue_chunk(c + 1);
            asm volatile("cp.async.wait_group 1;" ::: "memory");
        } else {
            asm volatile("cp.async.wait_group 0;" ::: "memory");
        }
        __syncthreads();

        uint32_t abase = sbase + (uint32_t)(c & 1) * BUF_BYTES;
        uint32_t bbase = abase + B_OFF;
#pragma unroll
        for (int ks = 0; ks < 64; ks += 16) {
            uint32_t ah[2][4], al[2][4], bh[4][2], bl[4][2];
#pragma unroll
            for (int mi = 0; mi < 2; mi++) {
                uint32_t row = (uint32_t)(wm * 32 + mi * 16 + lm01 * 8 + lr);
                uint32_t col = (uint32_t)(ks + lm23 * 8);
                uint32_t off = row * ROWB + col * 2u;
                LDSM4(ah[mi][0], ah[mi][1], ah[mi][2], ah[mi][3], abase + off);
                LDSM4(al[mi][0], al[mi][1], al[mi][2], al[mi][3],
                      abase + A_PLANE + off);
            }
#pragma unroll
            for (int ng = 0; ng < 2; ng++) {
                uint32_t row = (uint32_t)(wn * 32 + ng * 16 + lm23 * 8 + lr);
                uint32_t col = (uint32_t)(ks + lm01 * 8);
                uint32_t off = row * ROWB + col * 2u;
                LDSM4(bh[2 * ng][0], bh[2 * ng][1], bh[2 * ng + 1][0],
                      bh[2 * ng + 1][1], bbase + off);
                LDSM4(bl[2 * ng][0], bl[2 * ng][1], bl[2 * ng + 1][0],
                      bl[2 * ng + 1][1], bbase + B_PLANE + off);
            }
#pragma unroll
            for (int mi = 0; mi < 2; mi++)
#pragma unroll
                for (int ni = 0; ni < 4; ni++)
                    MMA16816(acc[mi][ni], ah[mi], bh[ni]);
#pragma unroll
            for (int mi = 0; mi < 2; mi++)
#pragma unroll
                for (int ni = 0; ni < 4; ni++)
                    MMA16816(acc[mi][ni], ah[mi], bl[ni]);
#pragma unroll
            for (int mi = 0; mi < 2; mi++)
#pragma unroll
                for (int ni = 0; ni < 4; ni++)
                    MMA16816(acc[mi][ni], al[mi], bh[ni]);
        }
        __syncthreads();
    }

    // ---- epilogue: paired (q=0,1) stores, fast SiLU ----
#pragma unroll
    for (int mi = 0; mi < 2; mi++) {
#pragma unroll
        for (int ni = 0; ni < 4; ni++) {
#pragma unroll
            for (int h = 0; h < 2; h++) {
                int gm = m0 + wm * 32 + mi * 16 + g + h * 8;
                if (gm >= M) continue;
                int gn0 = n0 + wn * 32 + ni * 8 + tg * 2;
                if (gn0 >= N) continue;
                float v0 = acc[mi][ni][h * 2 + 0];
                float v1 = acc[mi][ni][h * 2 + 1];
                if (bias) { v0 += bias[gn0]; v1 += bias[gn0 + 1]; }
                if (ACT == 1) { v0 = fast_silu(v0); v1 = fast_silu(v1); }
                if (SPLIT_OUT == 1) {
                    __nv_bfloat16 h0 = __float2bfloat16(v0);
                    __nv_bfloat16 h1 = __float2bfloat16(v1);
                    __nv_bfloat162 hp; hp.x = h0; hp.y = h1;
                    *(__nv_bfloat162*)(Chi + (size_t)gm * N + gn0) = hp;
                    __nv_bfloat162 lp;
                    lp.x = __float2bfloat16(v0 - __bfloat162float(h0));
                    lp.y = __float2bfloat16(v1 - __bfloat162float(h1));
                    *(__nv_bfloat162*)(Clo + (size_t)gm * N + gn0) = lp;
                } else {
                    float2 fv = make_float2(v0, v1);
                    *(float2*)(Cf + (size_t)gm * N + gn0) = fv;
                }
            }
        }
    }
}

// ---------------- residual + LayerNorm (shuffle reductions) ----------------
__global__ void ln_kernel(const float* __restrict__ F, const float* __restrict__ h2,
                          const float* __restrict__ gamma, const float* __restrict__ beta,
                          float* __restrict__ out) {
    __shared__ float wred[8];
    int n = blockIdx.x;
    int tid = threadIdx.x;
    int lane = tid & 31;
    int wid = tid >> 5;
    float x = (tid < DD) ? (F[n * DD + tid] + h2[n * DD + tid]) : 0.f;

    float s = x;
#pragma unroll
    for (int o = 16; o > 0; o >>= 1) s += __shfl_xor_sync(0xFFFFFFFFu, s, o);
    if (lane == 0) wred[wid] = s;
    __syncthreads();
    float mu = 0.f;
#pragma unroll
    for (int i = 0; i < 8; i++) mu += wred[i];
    mu *= (1.f / DD);
    __syncthreads();

    float xc = (tid < DD) ? (x - mu) : 0.f;
    float s2 = xc * xc;
#pragma unroll
    for (int o = 16; o > 0; o >>= 1) s2 += __shfl_xor_sync(0xFFFFFFFFu, s2, o);
    if (lane == 0) wred[wid] = s2;
    __syncthreads();
    float var = 0.f;
#pragma unroll
    for (int i = 0; i < 8; i++) var += wred[i];
    var *= (1.f / DD);
    float r = rsqrtf(var + 1e-5f);
    if (tid < DD)
        out[n * DD + tid] = xc * r * gamma[tid] + beta[tid];
}

// ---------------- launcher ----------------
extern "C" void kernel_launch(void* const* d_in, const int* in_sizes, int n_in,
                              void* d_out, int out_size) {
    const float* features = (const float*)d_in[0];
    const int*   ei       = (const int*)d_in[1];
    const float* Wmsg     = (const float*)d_in[2];
    const float* W1       = (const float*)d_in[3];
    const float* b1       = (const float*)d_in[4];
    const float* W2       = (const float*)d_in[5];
    const float* b2       = (const float*)d_in[6];
    const float* gamma    = (const float*)d_in[7];
    const float* beta     = (const float*)d_in[8];
    const int*   Iv       = (const int*)d_in[9];
    const int*   Jv       = (const int*)d_in[10];
    const int*   Kv       = (const int*)d_in[11];
    const float* Cv       = (const float*)d_in[12];
    float* out = (float*)d_out;

    int N   = in_sizes[0] / DD;
    int E   = in_sizes[1] / 2;
    int nnz = in_sizes[9];

    float *p_proj, *p_S, *p_h2;
    __nv_bfloat16 *p_fhi, *p_flo, *p_agghi, *p_agglo, *p_hidhi, *p_hidlo;
    __nv_bfloat16 *p_wmhi, *p_wmlo, *p_w1hi, *p_w1lo, *p_w2hi, *p_w2lo;
    cudaGetSymbolAddress((void**)&p_proj,  g_proj);
    cudaGetSymbolAddress((void**)&p_S,     g_S);
    cudaGetSymbolAddress((void**)&p_h2,    g_h2);
    cudaGetSymbolAddress((void**)&p_fhi,   g_fhi);
    cudaGetSymbolAddress((void**)&p_flo,   g_flo);
    cudaGetSymbolAddress((void**)&p_agghi, g_agghi);
    cudaGetSymbolAddress((void**)&p_agglo, g_agglo);
    cudaGetSymbolAddress((void**)&p_hidhi, g_hidhi);
    cudaGetSymbolAddress((void**)&p_hidlo, g_hidlo);
    cudaGetSymbolAddress((void**)&p_wmhi,  g_wmhi);
    cudaGetSymbolAddress((void**)&p_wmlo,  g_wmlo);
    cudaGetSymbolAddress((void**)&p_w1hi,  g_w1hi);
    cudaGetSymbolAddress((void**)&p_w1lo,  g_w1lo);
    cudaGetSymbolAddress((void**)&p_w2hi,  g_w2hi);
    cudaGetSymbolAddress((void**)&p_w2lo,  g_w2lo);

    const int SMEM_SZ = NSTAGE * 55296;
    cudaFuncSetAttribute(hmma_gemm<0, 0>, cudaFuncAttributeMaxDynamicSharedMemorySize, SMEM_SZ);
    cudaFuncSetAttribute(hmma_gemm<1, 1>, cudaFuncAttributeMaxDynamicSharedMemorySize, SMEM_SZ);

    int csrBlocks = (nnz + 255) / 256;

    // #1: fused setup (CSR + all splits + zero S)
    combo_prep_kernel<<<512 + csrBlocks, 256>>>(
        features, Wmsg, W1, W2, Iv, Jv, Kv, Cv,
        p_fhi, p_flo, p_wmhi, p_wmlo, p_w1hi, p_w1lo, p_w2hi, p_w2lo,
        p_S, N * DD, nnz, csrBlocks);

    int mtiles = (N + 127) / 128;

    // #2: proj = features @ Wmsg^T
    hmma_gemm<0, 0><<<dim3(mtiles, (DD + 63) / 64), 256, SMEM_SZ>>>(
        p_fhi, p_flo, p_wmhi, p_wmlo, nullptr, p_proj, nullptr, nullptr, N, DD, DD);

    // #3: S[tgt] += proj[src]
    scatter_edges_kernel<<<(E + 3) / 4, 256>>>(ei, p_proj, p_S, E);

    // #4 (profiled): agg = bracket(S, features), pre-split
    bracket_kernel<<<N, 256>>>(p_S, features, p_agghi, p_agglo);

    // #5: hidden = silu(agg @ W1^T + b1), pre-split
    hmma_gemm<1, 1><<<dim3(mtiles, (HH + 63) / 64), 256, SMEM_SZ>>>(
        p_agghi, p_agglo, p_w1hi, p_w1lo, b1, nullptr, p_hidhi, p_hidlo, N, HH, DD);

    // #6: h2 = hidden @ W2^T + b2
    hmma_gemm<0, 0><<<dim3(mtiles, (DD + 63) / 64), 256, SMEM_SZ>>>(
        p_hidhi, p_hidlo, p_w2hi, p_w2lo, b2, p_h2, nullptr, nullptr, N, DD, HH);

    // #7: out = LayerNorm(features + h2)
    ln_kernel<<<N, 256>>>(features, p_h2, gamma, beta, out);
}

// round 17
// speedup vs baseline: 1.3906x; 1.1694x over previous
#include <cuda_runtime.h>
#include <cuda_bf16.h>
#include <math.h>
#include <stdint.h>

#define DD   248
#define HH   512
#define NMAX 10000
#define NNZMAX 4096
#define GNODES 16

// ---------------- scratch (device globals; no allocs allowed) ----------------
__device__ float g_proj[NMAX * DD];
__device__ float g_S[NMAX * DD];
__device__ float g_h2[NMAX * DD];
__device__ __align__(16) __nv_bfloat16 g_fhi[NMAX * DD];
__device__ __align__(16) __nv_bfloat16 g_flo[NMAX * DD];
__device__ __align__(16) __nv_bfloat16 g_agghi[NMAX * DD];
__device__ __align__(16) __nv_bfloat16 g_agglo[NMAX * DD];
__device__ __align__(16) __nv_bfloat16 g_hidhi[NMAX * HH];
__device__ __align__(16) __nv_bfloat16 g_hidlo[NMAX * HH];
__device__ __align__(16) __nv_bfloat16 g_wmhi[DD * DD];
__device__ __align__(16) __nv_bfloat16 g_wmlo[DD * DD];
__device__ __align__(16) __nv_bfloat16 g_w1hi[HH * DD];
__device__ __align__(16) __nv_bfloat16 g_w1lo[HH * DD];
__device__ __align__(16) __nv_bfloat16 g_w2hi[DD * HH];
__device__ __align__(16) __nv_bfloat16 g_w2lo[DD * HH];
__device__ int   g_rowptr[DD + 1];
__device__ int   g_Is[NNZMAX];
__device__ int   g_Js[NNZMAX];
__device__ float g_Cs[NNZMAX];

// ---------------- splits ----------------
__device__ __forceinline__ void split1(const float* __restrict__ x,
                                       __nv_bfloat16* __restrict__ hi,
                                       __nv_bfloat16* __restrict__ lo, int i) {
    float v = x[i];
    __nv_bfloat16 h = __float2bfloat16(v);
    hi[i] = h;
    lo[i] = __float2bfloat16(v - __bfloat162float(h));
}

// launch #1 (fused setup): blocks [0, csrBlocks) build the structure-constant
// CSR (stable rank-by-scan, deterministic); remaining blocks do all bf16
// splits + zero S in one grid-stride sweep.
__global__ void combo_prep_kernel(
    const float* __restrict__ F,
    const float* __restrict__ Wmsg,
    const float* __restrict__ W1,
    const float* __restrict__ W2,
    const int* __restrict__ Iv, const int* __restrict__ Jv,
    const int* __restrict__ Kv, const float* __restrict__ Cv,
    __nv_bfloat16* __restrict__ fhi, __nv_bfloat16* __restrict__ flo,
    __nv_bfloat16* __restrict__ wmhi, __nv_bfloat16* __restrict__ wmlo,
    __nv_bfloat16* __restrict__ w1hi, __nv_bfloat16* __restrict__ w1lo,
    __nv_bfloat16* __restrict__ w2hi, __nv_bfloat16* __restrict__ w2lo,
    float* __restrict__ S, int nfeat, int nnz, int csrBlocks)
{
    int tid = threadIdx.x;
    if (blockIdx.x < (unsigned)csrBlocks) {
        // ---- CSR path ----
        __shared__ int sK[NNZMAX];
        __shared__ int cnt[DD];
        __shared__ int off[DD + 1];
        for (int t = tid; t < nnz; t += blockDim.x) sK[t] = Kv[t];
        for (int k = tid; k < DD; k += blockDim.x) cnt[k] = 0;
        __syncthreads();
        for (int t = tid; t < nnz; t += blockDim.x) atomicAdd(&cnt[sK[t]], 1);
        __syncthreads();
        if (tid == 0) {
            int s = 0;
            for (int k = 0; k < DD; k++) { off[k] = s; s += cnt[k]; }
            off[DD] = s;
        }
        __syncthreads();
        if (blockIdx.x == 0)
            for (int k = tid; k <= DD; k += blockDim.x) g_rowptr[k] = off[k];
        int t = blockIdx.x * blockDim.x + tid;
        if (t < nnz) {
            int k = sK[t];
            int rank = 0;
            for (int t2 = 0; t2 < t; ++t2) rank += (sK[t2] == k);
            int pos = off[k] + rank;
            g_Is[pos] = Iv[t];
            g_Js[pos] = Jv[t];
            g_Cs[pos] = Cv[t];
        }
    } else {
        // ---- prep path ----
        const int s1 = DD * DD;
        const int s2 = HH * DD;
        const int s3 = DD * HH;
        int total = nfeat + s1 + s2 + s3;
        int nblocks = gridDim.x - csrBlocks;
        int i = (blockIdx.x - csrBlocks) * blockDim.x + tid;
        int stride = nblocks * blockDim.x;
        for (; i < total; i += stride) {
            if (i < nfeat) {
                split1(F, fhi, flo, i);
                S[i] = 0.f;
            } else if (i < nfeat + s1) {
                split1(Wmsg, wmhi, wmlo, i - nfeat);
            } else if (i < nfeat + s1 + s2) {
                split1(W1, w1hi, w1lo, i - nfeat - s1);
            } else {
                split1(W2, w2hi, w2lo, i - nfeat - s1 - s2);
            }
        }
    }
}

// S[tgt[e]] += proj[src[e]] : 4 edges per block, indices cached in smem,
// 64 threads per edge, float4 vectorized atomics.
__global__ void scatter_edges_kernel(const int* __restrict__ ei,
                                     const float* __restrict__ proj,
                                     float* __restrict__ S, int E) {
    __shared__ int sidx[8];
    int e0 = blockIdx.x * 4;
    int tid = threadIdx.x;
    if (tid < 8) {
        int slot = tid >> 1;
        int e = e0 + slot;
        int v = -1;
        if (e < E) v = (tid & 1) ? ei[E + e] : ei[e];
        sidx[tid] = v;
    }
    __syncthreads();
    int grp = tid >> 6;
    int c = tid & 63;
    int e = e0 + grp;
    if (e >= E || c >= DD / 4) return;
    int s = sidx[2 * grp];
    int t = sidx[2 * grp + 1];
    float4 v = *(const float4*)(proj + (size_t)s * DD + c * 4);
#if __CUDA_ARCH__ >= 900
    atomicAdd((float4*)(S + (size_t)t * DD + c * 4), v);
#else
    float* p = S + (size_t)t * DD + c * 4;
    atomicAdd(p + 0, v.x); atomicAdd(p + 1, v.y);
    atomicAdd(p + 2, v.z); atomicAdd(p + 3, v.w);
#endif
}

// ---- bracket v2: 16 nodes per block, triples register-cached --------------
// agg[n,k] = sum_t C_t * S[n,I_t] * f[n,J_t]; deterministic per-k order kept.
__global__ __launch_bounds__(256) void bracket_kernel(
    const float* __restrict__ S, const float* __restrict__ F,
    __nv_bfloat16* __restrict__ Ahi, __nv_bfloat16* __restrict__ Alo, int Nn) {
    __shared__ float sS[GNODES * DD];
    __shared__ float sF[GNODES * DD];
    int n0 = blockIdx.x * GNODES;
    int tid = threadIdx.x;
    // cooperative float4 load of 16 nodes (62 float4 per node per array)
    for (int i = tid; i < GNODES * (DD / 4); i += 256) {
        int g = i / (DD / 4);
        int c = i % (DD / 4);
        int n = n0 + g;
        if (n < Nn) {
            *(float4*)&sS[g * DD + c * 4] = *(const float4*)(S + (size_t)n * DD + c * 4);
            *(float4*)&sF[g * DD + c * 4] = *(const float4*)(F + (size_t)n * DD + c * 4);
        }
    }
    __syncthreads();
    if (tid < DD) {
        int b = g_rowptr[tid];
        int e = g_rowptr[tid + 1];
        float acc[GNODES];
#pragma unroll
        for (int g = 0; g < GNODES; g++) acc[g] = 0.f;
        for (int t = b; t < e; t++) {
            int I = g_Is[t];
            int J = g_Js[t];
            float C = g_Cs[t];
#pragma unroll
            for (int g = 0; g < GNODES; g++)
                acc[g] += C * sS[g * DD + I] * sF[g * DD + J];
        }
#pragma unroll
        for (int g = 0; g < GNODES; g++) {
            int n = n0 + g;
            if (n < Nn) {
                __nv_bfloat16 h = __float2bfloat16(acc[g]);
                Ahi[(size_t)n * DD + tid] = h;
                Alo[(size_t)n * DD + tid] =
                    __float2bfloat16(acc[g] - __bfloat162float(h));
            }
        }
    }
}

// fast SiLU: x * sigmoid(x) = 0.5*x*(1 + tanh(x/2)) using MUFU tanh.approx
__device__ __forceinline__ float fast_silu(float v) {
    float t;
    asm("tanh.approx.f32 %0, %1;" : "=f"(t) : "f"(v * 0.5f));
    return 0.5f * v * (1.0f + t);
}

// ---------------- warp-MMA (mma.sync bf16) split GEMM, BK=64 --------
#define MMA16816(c, a, b)                                                     \
    asm volatile(                                                             \
        "mma.sync.aligned.m16n8k16.row.col.f32.bf16.bf16.f32 "                \
        "{%0,%1,%2,%3},{%4,%5,%6,%7},{%8,%9},{%0,%1,%2,%3};"                  \
        : "+f"((c)[0]), "+f"((c)[1]), "+f"((c)[2]), "+f"((c)[3])              \
        : "r"((a)[0]), "r"((a)[1]), "r"((a)[2]), "r"((a)[3]),                 \
          "r"((b)[0]), "r"((b)[1]))

#define LDSM4(r0, r1, r2, r3, addr)                                           \
    asm volatile("ldmatrix.sync.aligned.m8n8.x4.shared.b16 {%0,%1,%2,%3}, [%4];" \
                 : "=r"(r0), "=r"(r1), "=r"(r2), "=r"(r3) : "r"(addr))

#define CPASYNC16(saddr, gaddr, sz)                                           \
    asm volatile("cp.async.cg.shared.global [%0], [%1], 16, %2;"              \
                 :: "r"(saddr), "l"(gaddr), "r"(sz) : "memory")

#define ROWB        144u
#define A_PLANE     18432u
#define B_OFF       36864u
#define B_PLANE     9216u
#define BUF_BYTES   55296u
#define NSTAGE      2

__device__ __forceinline__ uint32_t smem_u32(const void* p) {
    uint32_t a;
    asm("{ .reg .u64 t; cvta.to.shared.u64 t, %1; cvt.u32.u64 %0, t; }"
        : "=r"(a) : "l"(p));
    return a;
}

template <int ACT, int SPLIT_OUT>
__global__ __launch_bounds__(256) void hmma_gemm(
    const __nv_bfloat16* __restrict__ Ah, const __nv_bfloat16* __restrict__ Al,
    const __nv_bfloat16* __restrict__ Bh, const __nv_bfloat16* __restrict__ Bl,
    const float* __restrict__ bias,
    float* __restrict__ Cf,
    __nv_bfloat16* __restrict__ Chi, __nv_bfloat16* __restrict__ Clo,
    int M, int N, int K)
{
    extern __shared__ char smem[];
    uint32_t sbase = smem_u32(smem);

    int tid = threadIdx.x;
    int wid = tid >> 5;
    int lane = tid & 31;
    int g = lane >> 2;
    int tg = lane & 3;
    int wm = wid >> 1;
    int wn = wid & 1;
    int m0 = blockIdx.x * 128;
    int n0 = blockIdx.y * 64;

    int lr = lane & 7;
    int lm01 = (lane >> 3) & 1;
    int lm23 = lane >> 4;

    float acc[2][4][4];
#pragma unroll
    for (int mi = 0; mi < 2; mi++)
#pragma unroll
        for (int ni = 0; ni < 4; ni++)
#pragma unroll
            for (int q = 0; q < 4; q++) acc[mi][ni][q] = 0.f;

    int nkc = (K + 63) >> 6;

    auto issue_chunk = [&](int c) {
        int kc = c << 6;
        uint32_t bufb = sbase + (uint32_t)(c & 1) * BUF_BYTES;
#pragma unroll
        for (int r = 0; r < 8; ++r) {
            int i = tid + (r << 8);
            int plane = i >> 10;
            int row = (i >> 3) & 127;
            int seg = i & 7;
            int gm = m0 + row;
            int k = kc + seg * 8;
            const __nv_bfloat16* src = (plane ? Al : Ah) + (size_t)gm * K + k;
            uint32_t dst = bufb + (uint32_t)plane * A_PLANE + (uint32_t)row * ROWB
                           + (uint32_t)seg * 16u;
            uint32_t sz = (gm < M && k < K) ? 16u : 0u;
            CPASYNC16(dst, src, sz);
        }
#pragma unroll
        for (int r = 0; r < 4; ++r) {
            int i = tid + (r << 8);
            int plane = i >> 9;
            int row = (i >> 3) & 63;
            int seg = i & 7;
            int gn = n0 + row;
            int k = kc + seg * 8;
            const __nv_bfloat16* src = (plane ? Bl : Bh) + (size_t)gn * K + k;
            uint32_t dst = bufb + B_OFF + (uint32_t)plane * B_PLANE
                           + (uint32_t)row * ROWB + (uint32_t)seg * 16u;
            uint32_t sz = (gn < N && k < K) ? 16u : 0u;
            CPASYNC16(dst, src, sz);
        }
        asm volatile("cp.async.commit_group;" ::: "memory");
    };

    issue_chunk(0);

    for (int c = 0; c < nkc; ++c) {
        if (c + 1 < nkc) {
            issue_chunk(c + 1);
            asm volatile("cp.async.wait_group 1;" ::: "memory");
        } else {
            asm volatile("cp.async.wait_group 0;" ::: "memory");
        }
        __syncthreads();

        uint32_t abase = sbase + (uint32_t)(c & 1) * BUF_BYTES;
        uint32_t bbase = abase + B_OFF;
#pragma unroll
        for (int ks = 0; ks < 64; ks += 16) {
            uint32_t ah[2][4], al[2][4], bh[4][2], bl[4][2];
#pragma unroll
            for (int mi = 0; mi < 2; mi++) {
                uint32_t row = (uint32_t)(wm * 32 + mi * 16 + lm01 * 8 + lr);
                uint32_t col = (uint32_t)(ks + lm23 * 8);
                uint32_t off = row * ROWB + col * 2u;
                LDSM4(ah[mi][0], ah[mi][1], ah[mi][2], ah[mi][3], abase + off);
                LDSM4(al[mi][0], al[mi][1], al[mi][2], al[mi][3],
                      abase + A_PLANE + off);
            }
#pragma unroll
            for (int ng = 0; ng < 2; ng++) {
                uint32_t row = (uint32_t)(wn * 32 + ng * 16 + lm23 * 8 + lr);
                uint32_t col = (uint32_t)(ks + lm01 * 8);
                uint32_t off = row * ROWB + col * 2u;
                LDSM4(bh[2 * ng][0], bh[2 * ng][1], bh[2 * ng + 1][0],
                      bh[2 * ng + 1][1], bbase + off);
                LDSM4(bl[2 * ng][0], bl[2 * ng][1], bl[2 * ng + 1][0],
                      bl[2 * ng + 1][1], bbase + B_PLANE + off);
            }
#pragma unroll
            for (int mi = 0; mi < 2; mi++)
#pragma unroll
                for (int ni = 0; ni < 4; ni++)
                    MMA16816(acc[mi][ni], ah[mi], bh[ni]);
#pragma unroll
            for (int mi = 0; mi < 2; mi++)
#pragma unroll
                for (int ni = 0; ni < 4; ni++)
                    MMA16816(acc[mi][ni], ah[mi], bl[ni]);
#pragma unroll
            for (int mi = 0; mi < 2; mi++)
#pragma unroll
                for (int ni = 0; ni < 4; ni++)
                    MMA16816(acc[mi][ni], al[mi], bh[ni]);
        }
        __syncthreads();
    }

    // ---- epilogue: paired (q=0,1) stores, fast SiLU ----
#pragma unroll
    for (int mi = 0; mi < 2; mi++) {
#pragma unroll
        for (int ni = 0; ni < 4; ni++) {
#pragma unroll
            for (int h = 0; h < 2; h++) {
                int gm = m0 + wm * 32 + mi * 16 + g + h * 8;
                if (gm >= M) continue;
                int gn0 = n0 + wn * 32 + ni * 8 + tg * 2;
                if (gn0 >= N) continue;
                float v0 = acc[mi][ni][h * 2 + 0];
                float v1 = acc[mi][ni][h * 2 + 1];
                if (bias) { v0 += bias[gn0]; v1 += bias[gn0 + 1]; }
                if (ACT == 1) { v0 = fast_silu(v0); v1 = fast_silu(v1); }
                if (SPLIT_OUT == 1) {
                    __nv_bfloat16 h0 = __float2bfloat16(v0);
                    __nv_bfloat16 h1 = __float2bfloat16(v1);
                    __nv_bfloat162 hp; hp.x = h0; hp.y = h1;
                    *(__nv_bfloat162*)(Chi + (size_t)gm * N + gn0) = hp;
                    __nv_bfloat162 lp;
                    lp.x = __float2bfloat16(v0 - __bfloat162float(h0));
                    lp.y = __float2bfloat16(v1 - __bfloat162float(h1));
                    *(__nv_bfloat162*)(Clo + (size_t)gm * N + gn0) = lp;
                } else {
                    float2 fv = make_float2(v0, v1);
                    *(float2*)(Cf + (size_t)gm * N + gn0) = fv;
                }
            }
        }
    }
}

// ---------------- residual + LayerNorm (shuffle reductions) ----------------
__global__ void ln_kernel(const float* __restrict__ F, const float* __restrict__ h2,
                          const float* __restrict__ gamma, const float* __restrict__ beta,
                          float* __restrict__ out) {
    __shared__ float wred[8];
    int n = blockIdx.x;
    int tid = threadIdx.x;
    int lane = tid & 31;
    int wid = tid >> 5;
    float x = (tid < DD) ? (F[n * DD + tid] + h2[n * DD + tid]) : 0.f;

    float s = x;
#pragma unroll
    for (int o = 16; o > 0; o >>= 1) s += __shfl_xor_sync(0xFFFFFFFFu, s, o);
    if (lane == 0) wred[wid] = s;
    __syncthreads();
    float mu = 0.f;
#pragma unroll
    for (int i = 0; i < 8; i++) mu += wred[i];
    mu *= (1.f / DD);
    __syncthreads();

    float xc = (tid < DD) ? (x - mu) : 0.f;
    float s2 = xc * xc;
#pragma unroll
    for (int o = 16; o > 0; o >>= 1) s2 += __shfl_xor_sync(0xFFFFFFFFu, s2, o);
    if (lane == 0) wred[wid] = s2;
    __syncthreads();
    float var = 0.f;
#pragma unroll
    for (int i = 0; i < 8; i++) var += wred[i];
    var *= (1.f / DD);
    float r = rsqrtf(var + 1e-5f);
    if (tid < DD)
        out[n * DD + tid] = xc * r * gamma[tid] + beta[tid];
}

// ---------------- launcher ----------------
extern "C" void kernel_launch(void* const* d_in, const int* in_sizes, int n_in,
                              void* d_out, int out_size) {
    const float* features = (const float*)d_in[0];
    const int*   ei       = (const int*)d_in[1];
    const float* Wmsg     = (const float*)d_in[2];
    const float* W1       = (const float*)d_in[3];
    const float* b1       = (const float*)d_in[4];
    const float* W2       = (const float*)d_in[5];
    const float* b2       = (const float*)d_in[6];
    const float* gamma    = (const float*)d_in[7];
    const float* beta     = (const float*)d_in[8];
    const int*   Iv       = (const int*)d_in[9];
    const int*   Jv       = (const int*)d_in[10];
    const int*   Kv       = (const int*)d_in[11];
    const float* Cv       = (const float*)d_in[12];
    float* out = (float*)d_out;

    int N   = in_sizes[0] / DD;
    int E   = in_sizes[1] / 2;
    int nnz = in_sizes[9];

    float *p_proj, *p_S, *p_h2;
    __nv_bfloat16 *p_fhi, *p_flo, *p_agghi, *p_agglo, *p_hidhi, *p_hidlo;
    __nv_bfloat16 *p_wmhi, *p_wmlo, *p_w1hi, *p_w1lo, *p_w2hi, *p_w2lo;
    cudaGetSymbolAddress((void**)&p_proj,  g_proj);
    cudaGetSymbolAddress((void**)&p_S,     g_S);
    cudaGetSymbolAddress((void**)&p_h2,    g_h2);
    cudaGetSymbolAddress((void**)&p_fhi,   g_fhi);
    cudaGetSymbolAddress((void**)&p_flo,   g_flo);
    cudaGetSymbolAddress((void**)&p_agghi, g_agghi);
    cudaGetSymbolAddress((void**)&p_agglo, g_agglo);
    cudaGetSymbolAddress((void**)&p_hidhi, g_hidhi);
    cudaGetSymbolAddress((void**)&p_hidlo, g_hidlo);
    cudaGetSymbolAddress((void**)&p_wmhi,  g_wmhi);
    cudaGetSymbolAddress((void**)&p_wmlo,  g_wmlo);
    cudaGetSymbolAddress((void**)&p_w1hi,  g_w1hi);
    cudaGetSymbolAddress((void**)&p_w1lo,  g_w1lo);
    cudaGetSymbolAddress((void**)&p_w2hi,  g_w2hi);
    cudaGetSymbolAddress((void**)&p_w2lo,  g_w2lo);

    const int SMEM_SZ = NSTAGE * 55296;
    cudaFuncSetAttribute(hmma_gemm<0, 0>, cudaFuncAttributeMaxDynamicSharedMemorySize, SMEM_SZ);
    cudaFuncSetAttribute(hmma_gemm<1, 1>, cudaFuncAttributeMaxDynamicSharedMemorySize, SMEM_SZ);

    int csrBlocks = (nnz + 255) / 256;

    // #1: fused setup (CSR + all splits + zero S)
    combo_prep_kernel<<<512 + csrBlocks, 256>>>(
        features, Wmsg, W1, W2, Iv, Jv, Kv, Cv,
        p_fhi, p_flo, p_wmhi, p_wmlo, p_w1hi, p_w1lo, p_w2hi, p_w2lo,
        p_S, N * DD, nnz, csrBlocks);

    int mtiles = (N + 127) / 128;

    // #2: proj = features @ Wmsg^T
    hmma_gemm<0, 0><<<dim3(mtiles, (DD + 63) / 64), 256, SMEM_SZ>>>(
        p_fhi, p_flo, p_wmhi, p_wmlo, nullptr, p_proj, nullptr, nullptr, N, DD, DD);

    // #3: S[tgt] += proj[src]
    scatter_edges_kernel<<<(E + 3) / 4, 256>>>(ei, p_proj, p_S, E);

    // #4 (profiled): agg = bracket(S, features), 16 nodes/block, pre-split
    bracket_kernel<<<(N + GNODES - 1) / GNODES, 256>>>(p_S, features,
                                                       p_agghi, p_agglo, N);

    // #5: hidden = silu(agg @ W1^T + b1), pre-split
    hmma_gemm<1, 1><<<dim3(mtiles, (HH + 63) / 64), 256, SMEM_SZ>>>(
        p_agghi, p_agglo, p_w1hi, p_w1lo, b1, nullptr, p_hidhi, p_hidlo, N, HH, DD);

    // #6: h2 = hidden @ W2^T + b2
    hmma_gemm<0, 0><<<dim3(mtiles, (DD + 63) / 64), 256, SMEM_SZ>>>(
        p_hidhi, p_hidlo, p_w2hi, p_w2lo, b2, p_h2, nullptr, nullptr, N, DD, HH);

    // #7: out = LayerNorm(features + h2)
    ln_kernel<<<N, 256>>>(features, p_h2, gamma, beta, out);
}